// round 4
// baseline (speedup 1.0000x reference)
#include <cuda_runtime.h>
#include <cuda_bf16.h>
#include <math.h>
#include <stdint.h>

#define T_SEQ   1536
#define DMODEL  2880
#define QKVD    5120
#define NH      64
#define NKV     8
#define HD      64
#define WIN     128
#define NEG_INF -1e30f
#define N2PAD   2944

// ---------------------------------------------------------------------------
// scratch
// ---------------------------------------------------------------------------
__device__ __align__(16) float g_qkv[T_SEQ * QKVD];
__device__ __align__(16) __nv_bfloat16 g_xhi[T_SEQ * DMODEL];
__device__ __align__(16) __nv_bfloat16 g_xlo[T_SEQ * DMODEL];
__device__ __align__(16) __nv_bfloat16 g_w1hi[QKVD * DMODEL];     // [N=5120, K=2880]
__device__ __align__(16) __nv_bfloat16 g_w1lo[QKVD * DMODEL];
__device__ __align__(16) __nv_bfloat16 g_w2hi[N2PAD * (NH * HD)]; // [N, K=4096]
__device__ __align__(16) __nv_bfloat16 g_w2lo[N2PAD * (NH * HD)];
__device__ __align__(16) __nv_bfloat16 g_ahi[T_SEQ * NH * HD];
__device__ __align__(16) __nv_bfloat16 g_alo[T_SEQ * NH * HD];
__device__ float g_invf[32];
__device__ float g_conc;

// ---------------------------------------------------------------------------
// PTX helpers (family-generic sm_80+ only; compute_103 target rejects tcgen05)
// ---------------------------------------------------------------------------
__device__ __forceinline__ uint32_t smem_u32(const void* p) {
    uint32_t a;
    asm("{ .reg .u64 t; cvta.to.shared.u64 t, %1; cvt.u32.u64 %0, t; }" : "=r"(a) : "l"(p));
    return a;
}
#define CP_ASYNC16(dst, src) \
    asm volatile("cp.async.cg.shared.global [%0], [%1], 16;" :: "r"(dst), "l"(src))
#define CP_COMMIT() asm volatile("cp.async.commit_group;" ::: "memory")
#define CP_WAIT(n)  asm volatile("cp.async.wait_group %0;" :: "n"(n) : "memory")
#define LDSM4(r0, r1, r2, r3, addr) \
    asm volatile("ldmatrix.sync.aligned.m8n8.x4.shared.b16 {%0,%1,%2,%3}, [%4];" \
        : "=r"(r0), "=r"(r1), "=r"(r2), "=r"(r3) : "r"(addr))
#define MMA16816(d, a, b) \
    asm volatile("mma.sync.aligned.m16n8k16.row.col.f32.bf16.bf16.f32 " \
        "{%0,%1,%2,%3}, {%4,%5,%6,%7}, {%8,%9}, {%0,%1,%2,%3};" \
        : "+f"((d)[0]), "+f"((d)[1]), "+f"((d)[2]), "+f"((d)[3]) \
        : "r"((a)[0]), "r"((a)[1]), "r"((a)[2]), "r"((a)[3]), "r"((b)[0]), "r"((b)[1]))

// smem geometry: per stage [Ahi 128x80][Alo 128x80][Bhi 64x80][Blo 64x80]
#define ROW_B    80
#define A_TILE_B (128 * ROW_B)                 // 10240
#define B_TILE_B (64 * ROW_B)                  // 5120
#define STAGE_B  (2 * A_TILE_B + 2 * B_TILE_B) // 30720
#define GEMM_SMEM (2 * STAGE_B)                // 61440

// ---------------------------------------------------------------------------
// HMMA bf16-split GEMM: C[M,N] = (Ahi+Alo)[M,K] @ (Bhi+Blo)[N,K]^T + bias
// 3 products, fp32 accum. CTA: 128 thr, tile 128x64, K-chunk 32, 2 stages.
// M % 128 == 0, N % 64 == 0, K % 32 == 0, nch >= 2.
// ---------------------------------------------------------------------------
__global__ __launch_bounds__(128, 2)
void gemm_hmma(int M, int N, int K,
               const __nv_bfloat16* __restrict__ Ahi, const __nv_bfloat16* __restrict__ Alo,
               const __nv_bfloat16* __restrict__ Bhi, const __nv_bfloat16* __restrict__ Blo,
               const float* __restrict__ bias, float* __restrict__ C)
{
    extern __shared__ char smem[];
    const uint32_t sb = smem_u32(smem);
    const int tid = threadIdx.x;
    const int wid = tid >> 5, lane = tid & 31;
    const int wm = wid & 1, wn = wid >> 1;          // 2 x 2 warp grid
    const int bm = blockIdx.y * 128, bn = blockIdx.x * 64;

    // cp.async assignment:
    //  A tiles: thread t loads full 64B row t (4 x 16B)
    //  B tiles: thread t loads 32B of row t>>1 (2 x 16B)
    const uint32_t a_dst = sb + tid * ROW_B;
    const uint32_t b_dst = sb + (tid >> 1) * ROW_B + (tid & 1) * 32;
    const size_t a_goff = (size_t)(bm + tid) * K;
    const size_t b_goff = (size_t)(bn + (tid >> 1)) * K + (tid & 1) * 16;

    // ldmatrix lane addressing
    const int a_row  = wm * 64 + (lane & 7) + (lane & 8);
    const int a_koff = ((lane >> 4) & 1) * 16;
    const int b_row  = wn * 32 + (lane & 7) + ((lane >> 4) & 1) * 8;
    const int b_koff = ((lane >> 3) & 1) * 16;

    float acc[4][4][4];
    #pragma unroll
    for (int i = 0; i < 4; i++)
        #pragma unroll
        for (int j = 0; j < 4; j++)
            #pragma unroll
            for (int r = 0; r < 4; r++) acc[i][j][r] = 0.0f;

    const int nch = K >> 5;

    auto load_stage = [&](int s, int c) {
        const uint32_t st = s * STAGE_B;
        const int kc = c * 32;
        const __nv_bfloat16* pa0 = Ahi + a_goff + kc;
        const __nv_bfloat16* pa1 = Alo + a_goff + kc;
        const __nv_bfloat16* pb0 = Bhi + b_goff + kc;
        const __nv_bfloat16* pb1 = Blo + b_goff + kc;
        #pragma unroll
        for (int j = 0; j < 4; j++) {
            CP_ASYNC16(a_dst + st + j * 16,            pa0 + j * 8);
            CP_ASYNC16(a_dst + st + A_TILE_B + j * 16, pa1 + j * 8);
        }
        const uint32_t bd = b_dst + st + 2 * A_TILE_B;
        CP_ASYNC16(bd,                 pb0);
        CP_ASYNC16(bd + 16,            pb0 + 8);
        CP_ASYNC16(bd + B_TILE_B,      pb1);
        CP_ASYNC16(bd + B_TILE_B + 16, pb1 + 8);
    };

    load_stage(0, 0); CP_COMMIT();
    load_stage(1, 1); CP_COMMIT();

    for (int c = 0; c < nch; c++) {
        const int s = c & 1;
        if (c + 1 < nch) { CP_WAIT(1); } else { CP_WAIT(0); }
        __syncthreads();                           // stage s visible to all warps

        // load ALL fragments for both k16 steps of this chunk
        const uint32_t stg = sb + s * STAGE_B;
        uint32_t ah[2][4][4], al[2][4][4], bh[2][4][2], bl[2][4][2];
        #pragma unroll
        for (int kk = 0; kk < 2; kk++) {
            const uint32_t a_k = a_koff + kk * 32;
            const uint32_t b_k = b_koff + kk * 32;
            #pragma unroll
            for (int tm = 0; tm < 4; tm++) {
                const uint32_t ra = stg + (a_row + tm * 16) * ROW_B + a_k;
                LDSM4(ah[kk][tm][0], ah[kk][tm][1], ah[kk][tm][2], ah[kk][tm][3], ra);
                LDSM4(al[kk][tm][0], al[kk][tm][1], al[kk][tm][2], al[kk][tm][3], ra + A_TILE_B);
            }
            #pragma unroll
            for (int bp = 0; bp < 2; bp++) {
                const uint32_t rb = stg + 2 * A_TILE_B + (b_row + bp * 16) * ROW_B + b_k;
                LDSM4(bh[kk][bp*2][0], bh[kk][bp*2][1], bh[kk][bp*2+1][0], bh[kk][bp*2+1][1], rb);
                LDSM4(bl[kk][bp*2][0], bl[kk][bp*2][1], bl[kk][bp*2+1][0], bl[kk][bp*2+1][1], rb + B_TILE_B);
            }
        }
        __syncthreads();                           // all warps done reading stage s
        if (c + 2 < nch) { load_stage(s, c + 2); CP_COMMIT(); }

        #pragma unroll
        for (int kk = 0; kk < 2; kk++)
            #pragma unroll
            for (int tm = 0; tm < 4; tm++)
                #pragma unroll
                for (int tn = 0; tn < 4; tn++) {
                    MMA16816(acc[tm][tn], ah[kk][tm], bh[kk][tn]);
                    MMA16816(acc[tm][tn], ah[kk][tm], bl[kk][tn]);
                    MMA16816(acc[tm][tn], al[kk][tm], bh[kk][tn]);
                }
    }

    // epilogue: registers -> global with bias
    const int r_base = bm + wm * 64 + (lane >> 2);
    const int c_base = bn + wn * 32 + (lane & 3) * 2;
    #pragma unroll
    for (int tm = 0; tm < 4; tm++) {
        #pragma unroll
        for (int tn = 0; tn < 4; tn++) {
            const int cc = c_base + tn * 8;
            const float2 bs = *(const float2*)&bias[cc];
            const int r0 = r_base + tm * 16;
            float2 v0, v1;
            v0.x = acc[tm][tn][0] + bs.x; v0.y = acc[tm][tn][1] + bs.y;
            v1.x = acc[tm][tn][2] + bs.x; v1.y = acc[tm][tn][3] + bs.y;
            *(float2*)&C[(size_t)r0 * N + cc]       = v0;
            *(float2*)&C[(size_t)(r0 + 8) * N + cc] = v1;
        }
    }
}

// ---------------------------------------------------------------------------
// fp32 -> bf16 hi/lo split (elementwise)
// ---------------------------------------------------------------------------
__global__ void convert_hilo(const float* __restrict__ in,
                             __nv_bfloat16* __restrict__ hi,
                             __nv_bfloat16* __restrict__ lo, int n)
{
    int i = blockIdx.x * blockDim.x + threadIdx.x;
    if (i >= n) return;
    float v = in[i];
    __nv_bfloat16 h = __float2bfloat16(v);
    hi[i] = h;
    lo[i] = __float2bfloat16(v - __bfloat162float(h));
}

// ---------------------------------------------------------------------------
// W [K,N] fp32 -> Thi/Tlo [Npad,K] bf16 (transpose + split; pad rows zeroed)
// ---------------------------------------------------------------------------
__global__ void transpose_convert(int K, int N, const float* __restrict__ W,
                                  __nv_bfloat16* __restrict__ Thi,
                                  __nv_bfloat16* __restrict__ Tlo)
{
    __shared__ float tile[32][33];
    const int k0 = blockIdx.y * 32, n0 = blockIdx.x * 32;
    const int tx = threadIdx.x, ty = threadIdx.y;
    #pragma unroll
    for (int i = 0; i < 32; i += 8) {
        const int k = k0 + ty + i;
        tile[ty + i][tx] = (n0 + tx < N) ? W[(size_t)k * N + n0 + tx] : 0.0f;
    }
    __syncthreads();
    #pragma unroll
    for (int i = 0; i < 32; i += 8) {
        const int n = n0 + ty + i;
        const float v = (n < N) ? tile[tx][ty + i] : 0.0f;
        const __nv_bfloat16 h = __float2bfloat16(v);
        Thi[(size_t)n * K + k0 + tx] = h;
        Tlo[(size_t)n * K + k0 + tx] = __float2bfloat16(v - __bfloat162float(h));
    }
}

// ---------------------------------------------------------------------------
// YaRN RoPE
// ---------------------------------------------------------------------------
__global__ void rope_init()
{
    const int i = threadIdx.x;
    const double TWO_PI = 6.283185307179586;
    double freq = pow(150000.0, (double)(2 * i) / 64.0);
    double conc = 0.1 * log(32.0) + 1.0;
    double lo   = 32.0 * log(1024.0 / (32.0 * TWO_PI)) / log(150000.0);
    double hi   = 32.0 * log(1024.0 / TWO_PI) / log(150000.0);
    double ramp = ((double)i - lo) / (hi - lo);
    ramp = fmin(1.0, fmax(0.0, ramp));
    g_invf[i] = (float)(ramp / (32.0 * freq) + (1.0 - ramp) / freq);
    if (i == 0) g_conc = (float)conc;
}

__global__ void rope_kernel(float* __restrict__ qkv)
{
    const int gid = blockIdx.x * blockDim.x + threadIdx.x;
    const int i   = gid & 31;
    const int hh  = (gid >> 5) % 72;
    const int t   = gid / (32 * 72);
    if (t >= T_SEQ) return;

    const float ang = (float)t * g_invf[i];
    const float cc  = g_conc;
    const float c   = cosf(ang) * cc;
    const float s   = sinf(ang) * cc;

    const int col = (hh < 64) ? hh * 64 : 4096 + (hh - 64) * 64;
    float* p = qkv + (size_t)t * QKVD + col;
    const float x1 = p[i];
    const float x2 = p[i + 32];
    p[i]      = x1 * c - x2 * s;
    p[i + 32] = x2 * c + x1 * s;
}

// ---------------------------------------------------------------------------
// Sliding-window GQA attention with sink logits.
// Output written directly as bf16 hi/lo (feeds gemm_hmma A operand).
// ---------------------------------------------------------------------------
__global__ __launch_bounds__(128)
void attn_kernel(const float* __restrict__ qkv, const float* __restrict__ sinks,
                 __nv_bfloat16* __restrict__ ahi, __nv_bfloat16* __restrict__ alo)
{
    __shared__ float Ks[WIN][HD + 1];
    __shared__ float wbuf[8][WIN];
    __shared__ float qs[8][HD];
    __shared__ float mxs[8], rds[8];

    const int i   = blockIdx.x;
    const int hkv = blockIdx.y;
    const int tid = threadIdx.x;

    int j0 = i - (WIN - 1);
    if (j0 < 0) j0 = 0;
    const int nk = i - j0 + 1;

    {
        const float* qp = qkv + (size_t)i * QKVD + hkv * 8 * 64;
        ((float4*)qs)[tid] = ((const float4*)qp)[tid];
    }
    for (int idx = tid; idx < nk * 64; idx += 128) {
        const int j = idx >> 6, d = idx & 63;
        Ks[j][d] = qkv[(size_t)(j0 + j) * QKVD + 4096 + hkv * 64 + d];
    }
    __syncthreads();

    float acc[8] = {0.f, 0.f, 0.f, 0.f, 0.f, 0.f, 0.f, 0.f};
    if (tid < nk) {
        #pragma unroll 8
        for (int d = 0; d < 64; d++) {
            const float kd = Ks[tid][d];
            #pragma unroll
            for (int m = 0; m < 8; m++) acc[m] = fmaf(kd, qs[m][d], acc[m]);
        }
    }
    #pragma unroll
    for (int m = 0; m < 8; m++)
        wbuf[m][tid] = (tid < nk) ? acc[m] * 0.125f : NEG_INF;
    __syncthreads();

    const int lane = tid & 31, wrp = tid >> 5;
    #pragma unroll
    for (int r = 0; r < 2; r++) {
        const int m = wrp * 2 + r;
        const float v0 = wbuf[m][lane],      v1 = wbuf[m][lane + 32];
        const float v2 = wbuf[m][lane + 64], v3 = wbuf[m][lane + 96];
        float mx = fmaxf(fmaxf(v0, v1), fmaxf(v2, v3));
        #pragma unroll
        for (int o = 16; o; o >>= 1) mx = fmaxf(mx, __shfl_xor_sync(0xffffffffu, mx, o));
        float sm = expf(v0 - mx) + expf(v1 - mx) + expf(v2 - mx) + expf(v3 - mx);
        #pragma unroll
        for (int o = 16; o; o >>= 1) sm += __shfl_xor_sync(0xffffffffu, sm, o);
        if (lane == 0) {
            const float denom = sm + expf(sinks[hkv * 8 + m] - mx);
            mxs[m] = mx;
            rds[m] = 1.0f / denom;
        }
    }
    __syncthreads();

    #pragma unroll
    for (int m = 0; m < 8; m++)
        wbuf[m][tid] = expf(wbuf[m][tid] - mxs[m]) * rds[m];
    __syncthreads();

    const int m  = tid >> 4;
    const int db = (tid & 15) * 4;
    float4 o = make_float4(0.f, 0.f, 0.f, 0.f);
    const float* vcol = qkv + 4608 + hkv * 64 + db;
    for (int j = 0; j < nk; j++) {
        const float wv = wbuf[m][j];
        const float4 v4 = *(const float4*)(vcol + (size_t)(j0 + j) * QKVD);
        o.x = fmaf(wv, v4.x, o.x);
        o.y = fmaf(wv, v4.y, o.y);
        o.z = fmaf(wv, v4.z, o.z);
        o.w = fmaf(wv, v4.w, o.w);
    }
    // fused hi/lo bf16 split
    const size_t oi = (size_t)i * (NH * HD) + (hkv * 8 + m) * 64 + db;
    __nv_bfloat16 h0 = __float2bfloat16(o.x), h1 = __float2bfloat16(o.y);
    __nv_bfloat16 h2 = __float2bfloat16(o.z), h3 = __float2bfloat16(o.w);
    __nv_bfloat162 hi01, hi23, lo01, lo23;
    hi01 = __nv_bfloat162(h0, h1);
    hi23 = __nv_bfloat162(h2, h3);
    lo01 = __nv_bfloat162(__float2bfloat16(o.x - __bfloat162float(h0)),
                          __float2bfloat16(o.y - __bfloat162float(h1)));
    lo23 = __nv_bfloat162(__float2bfloat16(o.z - __bfloat162float(h2)),
                          __float2bfloat16(o.w - __bfloat162float(h3)));
    *(__nv_bfloat162*)&ahi[oi]     = hi01;
    *(__nv_bfloat162*)&ahi[oi + 2] = hi23;
    *(__nv_bfloat162*)&alo[oi]     = lo01;
    *(__nv_bfloat162*)&alo[oi + 2] = lo23;
}

// ---------------------------------------------------------------------------
extern "C" void kernel_launch(void* const* d_in, const int* in_sizes, int n_in,
                              void* d_out, int out_size)
{
    (void)in_sizes; (void)n_in; (void)out_size;
    const float* x     = (const float*)d_in[0];
    const float* Wqkv  = (const float*)d_in[1];
    const float* bqkv  = (const float*)d_in[2];
    const float* Wout  = (const float*)d_in[3];
    const float* bout  = (const float*)d_in[4];
    const float* sinks = (const float*)d_in[5];
    float* out = (float*)d_out;

    void *p;
    cudaGetSymbolAddress(&p, g_qkv);  float* qkv = (float*)p;
    cudaGetSymbolAddress(&p, g_xhi);  __nv_bfloat16* xhi = (__nv_bfloat16*)p;
    cudaGetSymbolAddress(&p, g_xlo);  __nv_bfloat16* xlo = (__nv_bfloat16*)p;
    cudaGetSymbolAddress(&p, g_w1hi); __nv_bfloat16* w1hi = (__nv_bfloat16*)p;
    cudaGetSymbolAddress(&p, g_w1lo); __nv_bfloat16* w1lo = (__nv_bfloat16*)p;
    cudaGetSymbolAddress(&p, g_w2hi); __nv_bfloat16* w2hi = (__nv_bfloat16*)p;
    cudaGetSymbolAddress(&p, g_w2lo); __nv_bfloat16* w2lo = (__nv_bfloat16*)p;
    cudaGetSymbolAddress(&p, g_ahi);  __nv_bfloat16* ahi = (__nv_bfloat16*)p;
    cudaGetSymbolAddress(&p, g_alo);  __nv_bfloat16* alo = (__nv_bfloat16*)p;

    cudaFuncSetAttribute(gemm_hmma, cudaFuncAttributeMaxDynamicSharedMemorySize, GEMM_SMEM);

    // operand prep
    convert_hilo<<<(T_SEQ * DMODEL + 255) / 256, 256>>>(x, xhi, xlo, T_SEQ * DMODEL);
    transpose_convert<<<dim3(QKVD / 32, DMODEL / 32), dim3(32, 8)>>>(DMODEL, QKVD, Wqkv, w1hi, w1lo);
    transpose_convert<<<dim3(N2PAD / 32, (NH * HD) / 32), dim3(32, 8)>>>(NH * HD, DMODEL, Wout, w2hi, w2lo);

    // 1) qkv = x @ W_qkv + b_qkv   (1536x5120x2880)
    gemm_hmma<<<dim3(QKVD / 64, T_SEQ / 128), 128, GEMM_SMEM>>>(
        T_SEQ, QKVD, DMODEL, xhi, xlo, w1hi, w1lo, bqkv, qkv);

    // 2) RoPE
    rope_init<<<1, 32>>>();
    rope_kernel<<<(T_SEQ * 72 * 32) / 256, 256>>>(qkv);

    // 3) attention (emits bf16 hi/lo directly)
    attn_kernel<<<dim3(T_SEQ, NKV), 128>>>(qkv, sinks, ahi, alo);

    // 4) out = att @ W_out + b_out (1536x2880x4096; 2880 % 64 == 0)
    gemm_hmma<<<dim3(DMODEL / 64, T_SEQ / 128), 128, GEMM_SMEM>>>(
        T_SEQ, DMODEL, NH * HD, ahi, alo, w2hi, w2lo, bout, out);
}

// round 5
// speedup vs baseline: 1.8148x; 1.8148x over previous
#include <cuda_runtime.h>
#include <cuda_bf16.h>
#include <math.h>
#include <stdint.h>

#define T_SEQ   1536
#define DMODEL  2880
#define QKVD    5120
#define NH      64
#define NKV     8
#define HD      64
#define WIN     128
#define NEG_INF -1e30f
#define N2PAD   2944

// ---------------------------------------------------------------------------
// scratch
// ---------------------------------------------------------------------------
__device__ __align__(16) float g_qkv[T_SEQ * QKVD];
__device__ __align__(16) __nv_bfloat16 g_xhi[T_SEQ * DMODEL];
__device__ __align__(16) __nv_bfloat16 g_xlo[T_SEQ * DMODEL];
__device__ __align__(16) __nv_bfloat16 g_w1hi[QKVD * DMODEL];     // [N=5120, K=2880]
__device__ __align__(16) __nv_bfloat16 g_w1lo[QKVD * DMODEL];
__device__ __align__(16) __nv_bfloat16 g_w2hi[N2PAD * (NH * HD)]; // [N, K=4096]
__device__ __align__(16) __nv_bfloat16 g_w2lo[N2PAD * (NH * HD)];
__device__ __align__(16) __nv_bfloat16 g_ahi[T_SEQ * NH * HD];
__device__ __align__(16) __nv_bfloat16 g_alo[T_SEQ * NH * HD];
__device__ float g_invf[32];
__device__ float g_conc;

// ---------------------------------------------------------------------------
// PTX helpers (family-generic sm_80+ only)
// ---------------------------------------------------------------------------
__device__ __forceinline__ uint32_t smem_u32(const void* p) {
    uint32_t a;
    asm("{ .reg .u64 t; cvta.to.shared.u64 t, %1; cvt.u32.u64 %0, t; }" : "=r"(a) : "l"(p));
    return a;
}
#define CP_ASYNC16(dst, src) \
    asm volatile("cp.async.cg.shared.global [%0], [%1], 16;" :: "r"(dst), "l"(src))
#define CP_COMMIT() asm volatile("cp.async.commit_group;" ::: "memory")
#define CP_WAIT(n)  asm volatile("cp.async.wait_group %0;" :: "n"(n) : "memory")
#define LDSM4(r0, r1, r2, r3, addr) \
    asm volatile("ldmatrix.sync.aligned.m8n8.x4.shared.b16 {%0,%1,%2,%3}, [%4];" \
        : "=r"(r0), "=r"(r1), "=r"(r2), "=r"(r3) : "r"(addr))
#define MMA16816(d, a, b) \
    asm volatile("mma.sync.aligned.m16n8k16.row.col.f32.bf16.bf16.f32 " \
        "{%0,%1,%2,%3}, {%4,%5,%6,%7}, {%8,%9}, {%0,%1,%2,%3};" \
        : "+f"((d)[0]), "+f"((d)[1]), "+f"((d)[2]), "+f"((d)[3]) \
        : "r"((a)[0]), "r"((a)[1]), "r"((a)[2]), "r"((a)[3]), "r"((b)[0]), "r"((b)[1]))

// smem: per stage [Ahi][Alo][Bhi][Blo], each 128 rows x 80B pitch (64B data)
#define ROW_B   80
#define TILE_B  (128 * ROW_B)          // 10240
#define STAGE_B (4 * TILE_B)           // 40960
#define GEMM_SMEM (2 * STAGE_B)        // 81920

// ---------------------------------------------------------------------------
// HMMA bf16-split GEMM: C[M,N] = (Ahi+Alo)[M,K] @ (Bhi+Blo)[N,K]^T + bias
// 3 products, fp32 accum. 256 thr, tile 128x128, K-chunk 32, double buffer.
// Coalesced cp.async: 4 lanes cover one 64B row (8 lines per instruction).
// M % 128 == 0, K % 32 == 0, B rows >= gridDim.x*128 (pad zero), GUARD_N.
// ---------------------------------------------------------------------------
template <int GUARD_N>
__global__ __launch_bounds__(256, 1)
void gemm_hmma(int M, int N, int K,
               const __nv_bfloat16* __restrict__ Ahi, const __nv_bfloat16* __restrict__ Alo,
               const __nv_bfloat16* __restrict__ Bhi, const __nv_bfloat16* __restrict__ Blo,
               const float* __restrict__ bias, float* __restrict__ C)
{
    extern __shared__ char smem[];
    const uint32_t sb = smem_u32(smem);
    const int tid = threadIdx.x;
    const int wid = tid >> 5, lane = tid & 31;
    const int wm = wid & 1, wn = wid >> 1;          // 2 x 4 warp grid
    const int bm = blockIdx.y * 128, bn = blockIdx.x * 128;

    // coalesced loader mapping: unit u in [0,512): row=u>>2, 16B-chunk=u&3.
    // thread handles u = tid and u = tid + 256  (rows r and r+64).
    const int ld_row = tid >> 2;                    // 0..63
    const int ld_c16 = tid & 3;                     // 0..3
    const uint32_t ld_dst = sb + ld_row * ROW_B + ld_c16 * 16;
    const size_t a_off0 = (size_t)(bm + ld_row) * K + ld_c16 * 8;
    const size_t a_off1 = (size_t)(bm + ld_row + 64) * K + ld_c16 * 8;
    const size_t b_off0 = (size_t)(bn + ld_row) * K + ld_c16 * 8;
    const size_t b_off1 = (size_t)(bn + ld_row + 64) * K + ld_c16 * 8;

    // ldmatrix lane addressing (verified R3 layout)
    const int a_row  = wm * 64 + (lane & 7) + (lane & 8);
    const int a_koff = ((lane >> 4) & 1) * 16;
    const int b_row  = wn * 32 + (lane & 7) + ((lane >> 4) & 1) * 8;
    const int b_koff = ((lane >> 3) & 1) * 16;

    float acc[4][4][4];
    #pragma unroll
    for (int i = 0; i < 4; i++)
        #pragma unroll
        for (int j = 0; j < 4; j++)
            #pragma unroll
            for (int r = 0; r < 4; r++) acc[i][j][r] = 0.0f;

    const int nch = K >> 5;

    auto load_stage = [&](int s, int c) {
        const uint32_t d0 = ld_dst + s * STAGE_B;
        const int kc = c * 32;
        CP_ASYNC16(d0 + 0 * TILE_B,            Ahi + a_off0 + kc);
        CP_ASYNC16(d0 + 0 * TILE_B + 64 * ROW_B, Ahi + a_off1 + kc);
        CP_ASYNC16(d0 + 1 * TILE_B,            Alo + a_off0 + kc);
        CP_ASYNC16(d0 + 1 * TILE_B + 64 * ROW_B, Alo + a_off1 + kc);
        CP_ASYNC16(d0 + 2 * TILE_B,            Bhi + b_off0 + kc);
        CP_ASYNC16(d0 + 2 * TILE_B + 64 * ROW_B, Bhi + b_off1 + kc);
        CP_ASYNC16(d0 + 3 * TILE_B,            Blo + b_off0 + kc);
        CP_ASYNC16(d0 + 3 * TILE_B + 64 * ROW_B, Blo + b_off1 + kc);
    };

    load_stage(0, 0);
    CP_COMMIT();

    for (int c = 0; c < nch; c++) {
        const int s = c & 1;
        if (c + 1 < nch) {
            load_stage(s ^ 1, c + 1);
            CP_COMMIT();
            CP_WAIT(1);
        } else {
            CP_WAIT(0);
        }
        __syncthreads();

        const uint32_t stg = sb + s * STAGE_B;
        #pragma unroll
        for (int kk = 0; kk < 2; kk++) {
            uint32_t ah[4][4], al[4][4], bh[4][2], bl[4][2];
            const uint32_t a_k = a_koff + kk * 32;
            const uint32_t b_k = b_koff + kk * 32;
            #pragma unroll
            for (int tm = 0; tm < 4; tm++) {
                const uint32_t ra = stg + (a_row + tm * 16) * ROW_B + a_k;
                LDSM4(ah[tm][0], ah[tm][1], ah[tm][2], ah[tm][3], ra);
                LDSM4(al[tm][0], al[tm][1], al[tm][2], al[tm][3], ra + TILE_B);
            }
            #pragma unroll
            for (int bp = 0; bp < 2; bp++) {
                const uint32_t rb = stg + 2 * TILE_B + (b_row + bp * 16) * ROW_B + b_k;
                LDSM4(bh[bp*2][0], bh[bp*2][1], bh[bp*2+1][0], bh[bp*2+1][1], rb);
                LDSM4(bl[bp*2][0], bl[bp*2][1], bl[bp*2+1][0], bl[bp*2+1][1], rb + TILE_B);
            }
            #pragma unroll
            for (int tm = 0; tm < 4; tm++)
                #pragma unroll
                for (int tn = 0; tn < 4; tn++) {
                    MMA16816(acc[tm][tn], ah[tm], bh[tn]);
                    MMA16816(acc[tm][tn], ah[tm], bl[tn]);
                    MMA16816(acc[tm][tn], al[tm], bh[tn]);
                }
        }
        __syncthreads();
    }

    // epilogue
    const int r_base = bm + wm * 64 + (lane >> 2);
    const int c_base = bn + wn * 32 + (lane & 3) * 2;
    #pragma unroll
    for (int tm = 0; tm < 4; tm++) {
        #pragma unroll
        for (int tn = 0; tn < 4; tn++) {
            const int cc = c_base + tn * 8;
            if (GUARD_N && cc >= N) continue;
            const float2 bs = *(const float2*)&bias[cc];
            const int r0 = r_base + tm * 16;
            float2 v0, v1;
            v0.x = acc[tm][tn][0] + bs.x; v0.y = acc[tm][tn][1] + bs.y;
            v1.x = acc[tm][tn][2] + bs.x; v1.y = acc[tm][tn][3] + bs.y;
            *(float2*)&C[(size_t)r0 * N + cc]       = v0;
            *(float2*)&C[(size_t)(r0 + 8) * N + cc] = v1;
        }
    }
}

// ---------------------------------------------------------------------------
// fp32 -> bf16 hi/lo split (elementwise)
// ---------------------------------------------------------------------------
__global__ void convert_hilo(const float* __restrict__ in,
                             __nv_bfloat16* __restrict__ hi,
                             __nv_bfloat16* __restrict__ lo, int n)
{
    int i = blockIdx.x * blockDim.x + threadIdx.x;
    if (i >= n) return;
    float v = in[i];
    __nv_bfloat16 h = __float2bfloat16(v);
    hi[i] = h;
    lo[i] = __float2bfloat16(v - __bfloat162float(h));
}

// ---------------------------------------------------------------------------
// W [K,N] fp32 -> Thi/Tlo [Npad,K] bf16 (transpose + split; pad rows zeroed)
// ---------------------------------------------------------------------------
__global__ void transpose_convert(int K, int N, const float* __restrict__ W,
                                  __nv_bfloat16* __restrict__ Thi,
                                  __nv_bfloat16* __restrict__ Tlo)
{
    __shared__ float tile[32][33];
    const int k0 = blockIdx.y * 32, n0 = blockIdx.x * 32;
    const int tx = threadIdx.x, ty = threadIdx.y;
    #pragma unroll
    for (int i = 0; i < 32; i += 8) {
        const int k = k0 + ty + i;
        tile[ty + i][tx] = (n0 + tx < N) ? W[(size_t)k * N + n0 + tx] : 0.0f;
    }
    __syncthreads();
    #pragma unroll
    for (int i = 0; i < 32; i += 8) {
        const int n = n0 + ty + i;
        const float v = (n < N) ? tile[tx][ty + i] : 0.0f;
        const __nv_bfloat16 h = __float2bfloat16(v);
        Thi[(size_t)n * K + k0 + tx] = h;
        Tlo[(size_t)n * K + k0 + tx] = __float2bfloat16(v - __bfloat162float(h));
    }
}

// ---------------------------------------------------------------------------
// YaRN RoPE
// ---------------------------------------------------------------------------
__global__ void rope_init()
{
    const int i = threadIdx.x;
    const double TWO_PI = 6.283185307179586;
    double freq = pow(150000.0, (double)(2 * i) / 64.0);
    double conc = 0.1 * log(32.0) + 1.0;
    double lo   = 32.0 * log(1024.0 / (32.0 * TWO_PI)) / log(150000.0);
    double hi   = 32.0 * log(1024.0 / TWO_PI) / log(150000.0);
    double ramp = ((double)i - lo) / (hi - lo);
    ramp = fmin(1.0, fmax(0.0, ramp));
    g_invf[i] = (float)(ramp / (32.0 * freq) + (1.0 - ramp) / freq);
    if (i == 0) g_conc = (float)conc;
}

__global__ void rope_kernel(float* __restrict__ qkv)
{
    const int gid = blockIdx.x * blockDim.x + threadIdx.x;
    const int i   = gid & 31;
    const int hh  = (gid >> 5) % 72;
    const int t   = gid / (32 * 72);
    if (t >= T_SEQ) return;

    const float ang = (float)t * g_invf[i];
    const float cc  = g_conc;
    const float c   = cosf(ang) * cc;
    const float s   = sinf(ang) * cc;

    const int col = (hh < 64) ? hh * 64 : 4096 + (hh - 64) * 64;
    float* p = qkv + (size_t)t * QKVD + col;
    const float x1 = p[i];
    const float x2 = p[i + 32];
    p[i]      = x1 * c - x2 * s;
    p[i + 32] = x2 * c + x1 * s;
}

// ---------------------------------------------------------------------------
// Sliding-window GQA attention with sink logits; emits bf16 hi/lo directly.
// ---------------------------------------------------------------------------
__global__ __launch_bounds__(128)
void attn_kernel(const float* __restrict__ qkv, const float* __restrict__ sinks,
                 __nv_bfloat16* __restrict__ ahi, __nv_bfloat16* __restrict__ alo)
{
    __shared__ float Ks[WIN][HD + 1];
    __shared__ float wbuf[8][WIN];
    __shared__ float qs[8][HD];
    __shared__ float mxs[8], rds[8];

    const int i   = blockIdx.x;
    const int hkv = blockIdx.y;
    const int tid = threadIdx.x;

    int j0 = i - (WIN - 1);
    if (j0 < 0) j0 = 0;
    const int nk = i - j0 + 1;

    {
        const float* qp = qkv + (size_t)i * QKVD + hkv * 8 * 64;
        ((float4*)qs)[tid] = ((const float4*)qp)[tid];
    }
    for (int idx = tid; idx < nk * 64; idx += 128) {
        const int j = idx >> 6, d = idx & 63;
        Ks[j][d] = qkv[(size_t)(j0 + j) * QKVD + 4096 + hkv * 64 + d];
    }
    __syncthreads();

    float acc[8] = {0.f, 0.f, 0.f, 0.f, 0.f, 0.f, 0.f, 0.f};
    if (tid < nk) {
        #pragma unroll 8
        for (int d = 0; d < 64; d++) {
            const float kd = Ks[tid][d];
            #pragma unroll
            for (int m = 0; m < 8; m++) acc[m] = fmaf(kd, qs[m][d], acc[m]);
        }
    }
    #pragma unroll
    for (int m = 0; m < 8; m++)
        wbuf[m][tid] = (tid < nk) ? acc[m] * 0.125f : NEG_INF;
    __syncthreads();

    const int lane = tid & 31, wrp = tid >> 5;
    #pragma unroll
    for (int r = 0; r < 2; r++) {
        const int m = wrp * 2 + r;
        const float v0 = wbuf[m][lane],      v1 = wbuf[m][lane + 32];
        const float v2 = wbuf[m][lane + 64], v3 = wbuf[m][lane + 96];
        float mx = fmaxf(fmaxf(v0, v1), fmaxf(v2, v3));
        #pragma unroll
        for (int o = 16; o; o >>= 1) mx = fmaxf(mx, __shfl_xor_sync(0xffffffffu, mx, o));
        float sm = expf(v0 - mx) + expf(v1 - mx) + expf(v2 - mx) + expf(v3 - mx);
        #pragma unroll
        for (int o = 16; o; o >>= 1) sm += __shfl_xor_sync(0xffffffffu, sm, o);
        if (lane == 0) {
            const float denom = sm + expf(sinks[hkv * 8 + m] - mx);
            mxs[m] = mx;
            rds[m] = 1.0f / denom;
        }
    }
    __syncthreads();

    #pragma unroll
    for (int m = 0; m < 8; m++)
        wbuf[m][tid] = expf(wbuf[m][tid] - mxs[m]) * rds[m];
    __syncthreads();

    const int m  = tid >> 4;
    const int db = (tid & 15) * 4;
    float4 o = make_float4(0.f, 0.f, 0.f, 0.f);
    const float* vcol = qkv + 4608 + hkv * 64 + db;
    for (int j = 0; j < nk; j++) {
        const float wv = wbuf[m][j];
        const float4 v4 = *(const float4*)(vcol + (size_t)(j0 + j) * QKVD);
        o.x = fmaf(wv, v4.x, o.x);
        o.y = fmaf(wv, v4.y, o.y);
        o.z = fmaf(wv, v4.z, o.z);
        o.w = fmaf(wv, v4.w, o.w);
    }
    const size_t oi = (size_t)i * (NH * HD) + (hkv * 8 + m) * 64 + db;
    __nv_bfloat16 h0 = __float2bfloat16(o.x), h1 = __float2bfloat16(o.y);
    __nv_bfloat16 h2 = __float2bfloat16(o.z), h3 = __float2bfloat16(o.w);
    *(__nv_bfloat162*)&ahi[oi]     = __nv_bfloat162(h0, h1);
    *(__nv_bfloat162*)&ahi[oi + 2] = __nv_bfloat162(h2, h3);
    *(__nv_bfloat162*)&alo[oi]     = __nv_bfloat162(
        __float2bfloat16(o.x - __bfloat162float(h0)),
        __float2bfloat16(o.y - __bfloat162float(h1)));
    *(__nv_bfloat162*)&alo[oi + 2] = __nv_bfloat162(
        __float2bfloat16(o.z - __bfloat162float(h2)),
        __float2bfloat16(o.w - __bfloat162float(h3)));
}

// ---------------------------------------------------------------------------
extern "C" void kernel_launch(void* const* d_in, const int* in_sizes, int n_in,
                              void* d_out, int out_size)
{
    (void)in_sizes; (void)n_in; (void)out_size;
    const float* x     = (const float*)d_in[0];
    const float* Wqkv  = (const float*)d_in[1];
    const float* bqkv  = (const float*)d_in[2];
    const float* Wout  = (const float*)d_in[3];
    const float* bout  = (const float*)d_in[4];
    const float* sinks = (const float*)d_in[5];
    float* out = (float*)d_out;

    void *p;
    cudaGetSymbolAddress(&p, g_qkv);  float* qkv = (float*)p;
    cudaGetSymbolAddress(&p, g_xhi);  __nv_bfloat16* xhi = (__nv_bfloat16*)p;
    cudaGetSymbolAddress(&p, g_xlo);  __nv_bfloat16* xlo = (__nv_bfloat16*)p;
    cudaGetSymbolAddress(&p, g_w1hi); __nv_bfloat16* w1hi = (__nv_bfloat16*)p;
    cudaGetSymbolAddress(&p, g_w1lo); __nv_bfloat16* w1lo = (__nv_bfloat16*)p;
    cudaGetSymbolAddress(&p, g_w2hi); __nv_bfloat16* w2hi = (__nv_bfloat16*)p;
    cudaGetSymbolAddress(&p, g_w2lo); __nv_bfloat16* w2lo = (__nv_bfloat16*)p;
    cudaGetSymbolAddress(&p, g_ahi);  __nv_bfloat16* ahi = (__nv_bfloat16*)p;
    cudaGetSymbolAddress(&p, g_alo);  __nv_bfloat16* alo = (__nv_bfloat16*)p;

    cudaFuncSetAttribute(gemm_hmma<0>, cudaFuncAttributeMaxDynamicSharedMemorySize, GEMM_SMEM);
    cudaFuncSetAttribute(gemm_hmma<1>, cudaFuncAttributeMaxDynamicSharedMemorySize, GEMM_SMEM);

    // operand prep
    convert_hilo<<<(T_SEQ * DMODEL + 255) / 256, 256>>>(x, xhi, xlo, T_SEQ * DMODEL);
    transpose_convert<<<dim3(QKVD / 32, DMODEL / 32), dim3(32, 8)>>>(DMODEL, QKVD, Wqkv, w1hi, w1lo);
    transpose_convert<<<dim3(N2PAD / 32, (NH * HD) / 32), dim3(32, 8)>>>(NH * HD, DMODEL, Wout, w2hi, w2lo);

    // 1) qkv = x @ W_qkv + b_qkv   (1536x5120x2880)
    gemm_hmma<0><<<dim3(QKVD / 128, T_SEQ / 128), 256, GEMM_SMEM>>>(
        T_SEQ, QKVD, DMODEL, xhi, xlo, w1hi, w1lo, bqkv, qkv);

    // 2) RoPE
    rope_init<<<1, 32>>>();
    rope_kernel<<<(T_SEQ * 72 * 32) / 256, 256>>>(qkv);

    // 3) attention (emits bf16 hi/lo directly)
    attn_kernel<<<dim3(T_SEQ, NKV), 128>>>(qkv, sinks, ahi, alo);

    // 4) out = att @ W_out + b_out (1536x2880x4096, N guarded)
    gemm_hmma<1><<<dim3(N2PAD / 128, T_SEQ / 128), 256, GEMM_SMEM>>>(
        T_SEQ, DMODEL, NH * HD, ahi, alo, w2hi, w2lo, bout, out);
}

// round 6
// speedup vs baseline: 1.9478x; 1.0733x over previous
#include <cuda_runtime.h>
#include <cuda_bf16.h>
#include <math.h>
#include <stdint.h>

#define T_SEQ   1536
#define DMODEL  2880
#define QKVD    5120
#define NH      64
#define NKV     8
#define HD      64
#define WIN     128
#define NEG_INF -1e30f
#define N2PAD   2944

// ---------------------------------------------------------------------------
// scratch
// ---------------------------------------------------------------------------
__device__ __align__(16) float g_qkv[T_SEQ * QKVD];
__device__ __align__(16) __nv_bfloat16 g_xhi[T_SEQ * DMODEL];
__device__ __align__(16) __nv_bfloat16 g_xlo[T_SEQ * DMODEL];
__device__ __align__(16) __nv_bfloat16 g_w1hi[QKVD * DMODEL];     // [N=5120, K=2880]
__device__ __align__(16) __nv_bfloat16 g_w1lo[QKVD * DMODEL];
__device__ __align__(16) __nv_bfloat16 g_w2hi[N2PAD * (NH * HD)]; // [N, K=4096]
__device__ __align__(16) __nv_bfloat16 g_w2lo[N2PAD * (NH * HD)];
__device__ __align__(16) __nv_bfloat16 g_ahi[T_SEQ * NH * HD];
__device__ __align__(16) __nv_bfloat16 g_alo[T_SEQ * NH * HD];
__device__ float g_invf[32];
__device__ float g_conc;

// ---------------------------------------------------------------------------
// PTX helpers (family-generic sm_80+ only)
// ---------------------------------------------------------------------------
__device__ __forceinline__ uint32_t smem_u32(const void* p) {
    uint32_t a;
    asm("{ .reg .u64 t; cvta.to.shared.u64 t, %1; cvt.u32.u64 %0, t; }" : "=r"(a) : "l"(p));
    return a;
}
#define CP_ASYNC16(dst, src) \
    asm volatile("cp.async.cg.shared.global [%0], [%1], 16;" :: "r"(dst), "l"(src))
#define CP_COMMIT() asm volatile("cp.async.commit_group;" ::: "memory")
#define CP_WAIT(n)  asm volatile("cp.async.wait_group %0;" :: "n"(n) : "memory")
#define LDSM4(r0, r1, r2, r3, addr) \
    asm volatile("ldmatrix.sync.aligned.m8n8.x4.shared.b16 {%0,%1,%2,%3}, [%4];" \
        : "=r"(r0), "=r"(r1), "=r"(r2), "=r"(r3) : "r"(addr))
#define MMA16816(d, a, b) \
    asm volatile("mma.sync.aligned.m16n8k16.row.col.f32.bf16.bf16.f32 " \
        "{%0,%1,%2,%3}, {%4,%5,%6,%7}, {%8,%9}, {%0,%1,%2,%3};" \
        : "+f"((d)[0]), "+f"((d)[1]), "+f"((d)[2]), "+f"((d)[3]) \
        : "r"((a)[0]), "r"((a)[1]), "r"((a)[2]), "r"((a)[3]), "r"((b)[0]), "r"((b)[1]))

// smem: per stage [Ahi][Alo][Bhi][Blo], each 128 rows x 80B pitch (64B data)
#define ROW_B   80
#define TILE_B  (128 * ROW_B)          // 10240
#define STAGE_B (4 * TILE_B)           // 40960
#define GEMM_SMEM (2 * STAGE_B)        // 81920

// ---------------------------------------------------------------------------
// HMMA bf16-split GEMM: C[M,N] = (Ahi+Alo)[M,K] @ (Bhi+Blo)[N,K]^T + bias
// 3 products, fp32 accum. 256 thr, tile 128x128, K-chunk 32, 2-stage pipe.
// Register-lean inner loop (B frags resident, A frags streamed) to fit
// 128 regs -> 2 CTAs/SM. One barrier per chunk.
// M % 128 == 0, K % 32 == 0, B rows >= gridDim.x*128 (pad zero), GUARD_N.
// ---------------------------------------------------------------------------
template <int GUARD_N>
__global__ __launch_bounds__(256, 2)
void gemm_hmma(int M, int N, int K,
               const __nv_bfloat16* __restrict__ Ahi, const __nv_bfloat16* __restrict__ Alo,
               const __nv_bfloat16* __restrict__ Bhi, const __nv_bfloat16* __restrict__ Blo,
               const float* __restrict__ bias, float* __restrict__ C)
{
    extern __shared__ char smem[];
    const uint32_t sb = smem_u32(smem);
    const int tid = threadIdx.x;
    const int wid = tid >> 5, lane = tid & 31;
    const int wm = wid & 1, wn = wid >> 1;          // 2 x 4 warp grid
    const int bm = blockIdx.y * 128, bn = blockIdx.x * 128;

    // coalesced loader: unit u in [0,512): row=u>>2, 16B-chunk=u&3
    const int ld_row = tid >> 2;
    const int ld_c16 = tid & 3;
    const uint32_t ld_dst = sb + ld_row * ROW_B + ld_c16 * 16;
    const size_t a_off0 = (size_t)(bm + ld_row) * K + ld_c16 * 8;
    const size_t a_off1 = (size_t)(bm + ld_row + 64) * K + ld_c16 * 8;
    const size_t b_off0 = (size_t)(bn + ld_row) * K + ld_c16 * 8;
    const size_t b_off1 = (size_t)(bn + ld_row + 64) * K + ld_c16 * 8;

    // ldmatrix lane addressing (verified layout)
    const int a_row  = wm * 64 + (lane & 7) + (lane & 8);
    const int a_koff = ((lane >> 4) & 1) * 16;
    const int b_row  = wn * 32 + (lane & 7) + ((lane >> 4) & 1) * 8;
    const int b_koff = ((lane >> 3) & 1) * 16;

    float acc[4][4][4];
    #pragma unroll
    for (int i = 0; i < 4; i++)
        #pragma unroll
        for (int j = 0; j < 4; j++)
            #pragma unroll
            for (int r = 0; r < 4; r++) acc[i][j][r] = 0.0f;

    const int nch = K >> 5;

    auto load_stage = [&](int s, int c) {
        const uint32_t d0 = ld_dst + s * STAGE_B;
        const int kc = c * 32;
        CP_ASYNC16(d0 + 0 * TILE_B,              Ahi + a_off0 + kc);
        CP_ASYNC16(d0 + 0 * TILE_B + 64 * ROW_B, Ahi + a_off1 + kc);
        CP_ASYNC16(d0 + 1 * TILE_B,              Alo + a_off0 + kc);
        CP_ASYNC16(d0 + 1 * TILE_B + 64 * ROW_B, Alo + a_off1 + kc);
        CP_ASYNC16(d0 + 2 * TILE_B,              Bhi + b_off0 + kc);
        CP_ASYNC16(d0 + 2 * TILE_B + 64 * ROW_B, Bhi + b_off1 + kc);
        CP_ASYNC16(d0 + 3 * TILE_B,              Blo + b_off0 + kc);
        CP_ASYNC16(d0 + 3 * TILE_B + 64 * ROW_B, Blo + b_off1 + kc);
    };

    load_stage(0, 0);
    CP_COMMIT();

    for (int c = 0; c < nch; c++) {
        const int s = c & 1;
        CP_WAIT(0);               // stage s data landed
        __syncthreads();          // + all warps done reading stage s^1
        if (c + 1 < nch) {
            load_stage(s ^ 1, c + 1);   // overlaps this chunk's compute
            CP_COMMIT();
        }

        const uint32_t stg = sb + s * STAGE_B;
        #pragma unroll
        for (int kk = 0; kk < 2; kk++) {
            const uint32_t a_k = a_koff + kk * 32;
            const uint32_t b_k = b_koff + kk * 32;
            // B fragments resident (16 regs)
            uint32_t bh[4][2], bl[4][2];
            #pragma unroll
            for (int bp = 0; bp < 2; bp++) {
                const uint32_t rb = stg + 2 * TILE_B + (b_row + bp * 16) * ROW_B + b_k;
                LDSM4(bh[bp*2][0], bh[bp*2][1], bh[bp*2+1][0], bh[bp*2+1][1], rb);
                LDSM4(bl[bp*2][0], bl[bp*2][1], bl[bp*2+1][0], bl[bp*2+1][1], rb + TILE_B);
            }
            // A fragments streamed per tm (8 regs live)
            #pragma unroll
            for (int tm = 0; tm < 4; tm++) {
                uint32_t ah[4], al[4];
                const uint32_t ra = stg + (a_row + tm * 16) * ROW_B + a_k;
                LDSM4(ah[0], ah[1], ah[2], ah[3], ra);
                LDSM4(al[0], al[1], al[2], al[3], ra + TILE_B);
                #pragma unroll
                for (int tn = 0; tn < 4; tn++) {
                    MMA16816(acc[tm][tn], ah, bh[tn]);
                    MMA16816(acc[tm][tn], ah, bl[tn]);
                    MMA16816(acc[tm][tn], al, bh[tn]);
                }
            }
        }
    }

    // epilogue
    const int r_base = bm + wm * 64 + (lane >> 2);
    const int c_base = bn + wn * 32 + (lane & 3) * 2;
    #pragma unroll
    for (int tm = 0; tm < 4; tm++) {
        #pragma unroll
        for (int tn = 0; tn < 4; tn++) {
            const int cc = c_base + tn * 8;
            if (GUARD_N && cc >= N) continue;
            const float2 bs = *(const float2*)&bias[cc];
            const int r0 = r_base + tm * 16;
            float2 v0, v1;
            v0.x = acc[tm][tn][0] + bs.x; v0.y = acc[tm][tn][1] + bs.y;
            v1.x = acc[tm][tn][2] + bs.x; v1.y = acc[tm][tn][3] + bs.y;
            *(float2*)&C[(size_t)r0 * N + cc]       = v0;
            *(float2*)&C[(size_t)(r0 + 8) * N + cc] = v1;
        }
    }
}

// ---------------------------------------------------------------------------
// fp32 -> bf16 hi/lo split (elementwise)
// ---------------------------------------------------------------------------
__global__ void convert_hilo(const float* __restrict__ in,
                             __nv_bfloat16* __restrict__ hi,
                             __nv_bfloat16* __restrict__ lo, int n)
{
    int i = blockIdx.x * blockDim.x + threadIdx.x;
    if (i >= n) return;
    float v = in[i];
    __nv_bfloat16 h = __float2bfloat16(v);
    hi[i] = h;
    lo[i] = __float2bfloat16(v - __bfloat162float(h));
}

// ---------------------------------------------------------------------------
// W [K,N] fp32 -> Thi/Tlo [Npad,K] bf16 (transpose + split; pad rows zeroed)
// ---------------------------------------------------------------------------
__global__ void transpose_convert(int K, int N, const float* __restrict__ W,
                                  __nv_bfloat16* __restrict__ Thi,
                                  __nv_bfloat16* __restrict__ Tlo)
{
    __shared__ float tile[32][33];
    const int k0 = blockIdx.y * 32, n0 = blockIdx.x * 32;
    const int tx = threadIdx.x, ty = threadIdx.y;
    #pragma unroll
    for (int i = 0; i < 32; i += 8) {
        const int k = k0 + ty + i;
        tile[ty + i][tx] = (n0 + tx < N) ? W[(size_t)k * N + n0 + tx] : 0.0f;
    }
    __syncthreads();
    #pragma unroll
    for (int i = 0; i < 32; i += 8) {
        const int n = n0 + ty + i;
        const float v = (n < N) ? tile[tx][ty + i] : 0.0f;
        const __nv_bfloat16 h = __float2bfloat16(v);
        Thi[(size_t)n * K + k0 + tx] = h;
        Tlo[(size_t)n * K + k0 + tx] = __float2bfloat16(v - __bfloat162float(h));
    }
}

// ---------------------------------------------------------------------------
// YaRN RoPE
// ---------------------------------------------------------------------------
__global__ void rope_init()
{
    const int i = threadIdx.x;
    const double TWO_PI = 6.283185307179586;
    double freq = pow(150000.0, (double)(2 * i) / 64.0);
    double conc = 0.1 * log(32.0) + 1.0;
    double lo   = 32.0 * log(1024.0 / (32.0 * TWO_PI)) / log(150000.0);
    double hi   = 32.0 * log(1024.0 / TWO_PI) / log(150000.0);
    double ramp = ((double)i - lo) / (hi - lo);
    ramp = fmin(1.0, fmax(0.0, ramp));
    g_invf[i] = (float)(ramp / (32.0 * freq) + (1.0 - ramp) / freq);
    if (i == 0) g_conc = (float)conc;
}

__global__ void rope_kernel(float* __restrict__ qkv)
{
    const int gid = blockIdx.x * blockDim.x + threadIdx.x;
    const int i   = gid & 31;
    const int hh  = (gid >> 5) % 72;
    const int t   = gid / (32 * 72);
    if (t >= T_SEQ) return;

    const float ang = (float)t * g_invf[i];
    const float cc  = g_conc;
    const float c   = cosf(ang) * cc;
    const float s   = sinf(ang) * cc;

    const int col = (hh < 64) ? hh * 64 : 4096 + (hh - 64) * 64;
    float* p = qkv + (size_t)t * QKVD + col;
    const float x1 = p[i];
    const float x2 = p[i + 32];
    p[i]      = x1 * c - x2 * s;
    p[i + 32] = x2 * c + x1 * s;
}

// ---------------------------------------------------------------------------
// Sliding-window GQA attention with sink logits; emits bf16 hi/lo directly.
// ---------------------------------------------------------------------------
__global__ __launch_bounds__(128)
void attn_kernel(const float* __restrict__ qkv, const float* __restrict__ sinks,
                 __nv_bfloat16* __restrict__ ahi, __nv_bfloat16* __restrict__ alo)
{
    __shared__ float Ks[WIN][HD + 1];
    __shared__ float wbuf[8][WIN];
    __shared__ float qs[8][HD];
    __shared__ float mxs[8], rds[8];

    const int i   = blockIdx.x;
    const int hkv = blockIdx.y;
    const int tid = threadIdx.x;

    int j0 = i - (WIN - 1);
    if (j0 < 0) j0 = 0;
    const int nk = i - j0 + 1;

    {
        const float* qp = qkv + (size_t)i * QKVD + hkv * 8 * 64;
        ((float4*)qs)[tid] = ((const float4*)qp)[tid];
    }
    for (int idx = tid; idx < nk * 64; idx += 128) {
        const int j = idx >> 6, d = idx & 63;
        Ks[j][d] = qkv[(size_t)(j0 + j) * QKVD + 4096 + hkv * 64 + d];
    }
    __syncthreads();

    float acc[8] = {0.f, 0.f, 0.f, 0.f, 0.f, 0.f, 0.f, 0.f};
    if (tid < nk) {
        #pragma unroll 8
        for (int d = 0; d < 64; d++) {
            const float kd = Ks[tid][d];
            #pragma unroll
            for (int m = 0; m < 8; m++) acc[m] = fmaf(kd, qs[m][d], acc[m]);
        }
    }
    #pragma unroll
    for (int m = 0; m < 8; m++)
        wbuf[m][tid] = (tid < nk) ? acc[m] * 0.125f : NEG_INF;
    __syncthreads();

    const int lane = tid & 31, wrp = tid >> 5;
    #pragma unroll
    for (int r = 0; r < 2; r++) {
        const int m = wrp * 2 + r;
        const float v0 = wbuf[m][lane],      v1 = wbuf[m][lane + 32];
        const float v2 = wbuf[m][lane + 64], v3 = wbuf[m][lane + 96];
        float mx = fmaxf(fmaxf(v0, v1), fmaxf(v2, v3));
        #pragma unroll
        for (int o = 16; o; o >>= 1) mx = fmaxf(mx, __shfl_xor_sync(0xffffffffu, mx, o));
        float sm = expf(v0 - mx) + expf(v1 - mx) + expf(v2 - mx) + expf(v3 - mx);
        #pragma unroll
        for (int o = 16; o; o >>= 1) sm += __shfl_xor_sync(0xffffffffu, sm, o);
        if (lane == 0) {
            const float denom = sm + expf(sinks[hkv * 8 + m] - mx);
            mxs[m] = mx;
            rds[m] = 1.0f / denom;
        }
    }
    __syncthreads();

    #pragma unroll
    for (int m = 0; m < 8; m++)
        wbuf[m][tid] = expf(wbuf[m][tid] - mxs[m]) * rds[m];
    __syncthreads();

    const int m  = tid >> 4;
    const int db = (tid & 15) * 4;
    float4 o = make_float4(0.f, 0.f, 0.f, 0.f);
    const float* vcol = qkv + 4608 + hkv * 64 + db;
    for (int j = 0; j < nk; j++) {
        const float wv = wbuf[m][j];
        const float4 v4 = *(const float4*)(vcol + (size_t)(j0 + j) * QKVD);
        o.x = fmaf(wv, v4.x, o.x);
        o.y = fmaf(wv, v4.y, o.y);
        o.z = fmaf(wv, v4.z, o.z);
        o.w = fmaf(wv, v4.w, o.w);
    }
    const size_t oi = (size_t)i * (NH * HD) + (hkv * 8 + m) * 64 + db;
    __nv_bfloat16 h0 = __float2bfloat16(o.x), h1 = __float2bfloat16(o.y);
    __nv_bfloat16 h2 = __float2bfloat16(o.z), h3 = __float2bfloat16(o.w);
    *(__nv_bfloat162*)&ahi[oi]     = __nv_bfloat162(h0, h1);
    *(__nv_bfloat162*)&ahi[oi + 2] = __nv_bfloat162(h2, h3);
    *(__nv_bfloat162*)&alo[oi]     = __nv_bfloat162(
        __float2bfloat16(o.x - __bfloat162float(h0)),
        __float2bfloat16(o.y - __bfloat162float(h1)));
    *(__nv_bfloat162*)&alo[oi + 2] = __nv_bfloat162(
        __float2bfloat16(o.z - __bfloat162float(h2)),
        __float2bfloat16(o.w - __bfloat162float(h3)));
}

// ---------------------------------------------------------------------------
extern "C" void kernel_launch(void* const* d_in, const int* in_sizes, int n_in,
                              void* d_out, int out_size)
{
    (void)in_sizes; (void)n_in; (void)out_size;
    const float* x     = (const float*)d_in[0];
    const float* Wqkv  = (const float*)d_in[1];
    const float* bqkv  = (const float*)d_in[2];
    const float* Wout  = (const float*)d_in[3];
    const float* bout  = (const float*)d_in[4];
    const float* sinks = (const float*)d_in[5];
    float* out = (float*)d_out;

    void *p;
    cudaGetSymbolAddress(&p, g_qkv);  float* qkv = (float*)p;
    cudaGetSymbolAddress(&p, g_xhi);  __nv_bfloat16* xhi = (__nv_bfloat16*)p;
    cudaGetSymbolAddress(&p, g_xlo);  __nv_bfloat16* xlo = (__nv_bfloat16*)p;
    cudaGetSymbolAddress(&p, g_w1hi); __nv_bfloat16* w1hi = (__nv_bfloat16*)p;
    cudaGetSymbolAddress(&p, g_w1lo); __nv_bfloat16* w1lo = (__nv_bfloat16*)p;
    cudaGetSymbolAddress(&p, g_w2hi); __nv_bfloat16* w2hi = (__nv_bfloat16*)p;
    cudaGetSymbolAddress(&p, g_w2lo); __nv_bfloat16* w2lo = (__nv_bfloat16*)p;
    cudaGetSymbolAddress(&p, g_ahi);  __nv_bfloat16* ahi = (__nv_bfloat16*)p;
    cudaGetSymbolAddress(&p, g_alo);  __nv_bfloat16* alo = (__nv_bfloat16*)p;

    cudaFuncSetAttribute(gemm_hmma<0>, cudaFuncAttributeMaxDynamicSharedMemorySize, GEMM_SMEM);
    cudaFuncSetAttribute(gemm_hmma<1>, cudaFuncAttributeMaxDynamicSharedMemorySize, GEMM_SMEM);

    // operand prep
    convert_hilo<<<(T_SEQ * DMODEL + 255) / 256, 256>>>(x, xhi, xlo, T_SEQ * DMODEL);
    transpose_convert<<<dim3(QKVD / 32, DMODEL / 32), dim3(32, 8)>>>(DMODEL, QKVD, Wqkv, w1hi, w1lo);
    transpose_convert<<<dim3(N2PAD / 32, (NH * HD) / 32), dim3(32, 8)>>>(NH * HD, DMODEL, Wout, w2hi, w2lo);

    // 1) qkv = x @ W_qkv + b_qkv   (1536x5120x2880)
    gemm_hmma<0><<<dim3(QKVD / 128, T_SEQ / 128), 256, GEMM_SMEM>>>(
        T_SEQ, QKVD, DMODEL, xhi, xlo, w1hi, w1lo, bqkv, qkv);

    // 2) RoPE
    rope_init<<<1, 32>>>();
    rope_kernel<<<(T_SEQ * 72 * 32) / 256, 256>>>(qkv);

    // 3) attention (emits bf16 hi/lo directly)
    attn_kernel<<<dim3(T_SEQ, NKV), 128>>>(qkv, sinks, ahi, alo);

    // 4) out = att @ W_out + b_out (1536x2880x4096, N guarded)
    gemm_hmma<1><<<dim3(N2PAD / 128, T_SEQ / 128), 256, GEMM_SMEM>>>(
        T_SEQ, DMODEL, NH * HD, ahi, alo, w2hi, w2lo, bout, out);
}